// round 12
// baseline (speedup 1.0000x reference)
#include <cuda_runtime.h>
#include <math.h>
#include <stdint.h>

#define Bn 256
#define Sn 256
#define Tn 32
#define Hn 512
#define En 128
#define EDn 32
#define An 8
#define NTn 80

__device__ float g_h[2][Bn*Hn];
__device__ float g_c[Bn*Hn];
__device__ float g_enc_out[(size_t)Sn*Bn*Hn];
__device__ float g_zx[1000*4*Hn];
__device__ float g_act_z[An*4*Hn];
__device__ float g_tgt_z[NTn*4*Hn];
__device__ float g_P[(size_t)Sn*Bn*96];
__device__ float g_wpad[128*Hn];
__device__ float g_wie_r[4*Hn*En];
__device__ float g_whe_r[4*Hn*Hn];
__device__ float g_whd_r[4*Hn*Hn];
__device__ float g_emb_r[1000*En];
__device__ int   g_inp[Bn*2];
__device__ int   g_bar[1152];   // [0..1023] enc: mgrp*256+t ; [1024..1087] dec

__device__ __forceinline__ float sigmoidf_(float x){ return 1.f/(1.f+expf(-x)); }
__device__ __forceinline__ float rna_f(float x){
    uint32_t u; asm("cvt.rna.tf32.f32 %0, %1;" : "=r"(u) : "f"(x));
    return __uint_as_float(u);
}
__device__ __forceinline__ uint32_t smem_u32(const void* p){
    uint32_t a;
    asm("{ .reg .u64 t; cvta.to.shared.u64 t, %1; cvt.u32.u64 %0, t; }" : "=r"(a) : "l"(p));
    return a;
}
#define CP_ASYNC16(dst, src) \
    asm volatile("cp.async.cg.shared.global [%0], [%1], 16;" :: "r"(dst), "l"(src))
#define CP_COMMIT() asm volatile("cp.async.commit_group;" ::: "memory")
#define CP_WAIT(n)  asm volatile("cp.async.wait_group %0;" :: "n"(n) : "memory")
#define MMA_TF32(d, a, b0v, b1v) \
    asm volatile("mma.sync.aligned.m16n8k8.row.col.f32.tf32.tf32.f32 " \
        "{%0,%1,%2,%3}, {%4,%5,%6,%7}, {%8,%9}, {%0,%1,%2,%3};" \
        : "+f"((d)[0]),"+f"((d)[1]),"+f"((d)[2]),"+f"((d)[3]) \
        : "r"((a)[0]),"r"((a)[1]),"r"((a)[2]),"r"((a)[3]), "r"(b0v),"r"(b1v))

__device__ __forceinline__ void gbar(int idx, int nc){
    __syncthreads();
    if (threadIdx.x == 0){
        int* p = &g_bar[idx];
        asm volatile("red.release.gpu.global.add.u32 [%0], 1;" :: "l"(p) : "memory");
        uint32_t v;
        do {
            asm volatile("ld.acquire.gpu.global.u32 %0, [%1];" : "=r"(v) : "l"(p) : "memory");
        } while (v < (uint32_t)nc);
    }
    __syncthreads();
}

__global__ void init_k(){
    int i = blockIdx.x*blockDim.x + threadIdx.x;
    if (i < Bn*Hn){ g_h[0][i]=0.f; g_h[1][i]=0.f; g_c[i]=0.f; }
    if (i < Bn*2) g_inp[i]=0;
    if (i < 1152) g_bar[i]=0;
}

// pre-encoder setup: round Wh_e, Wi_e, enc_embed   (grid 4096 x 256)
__global__ void pre_k(const float* __restrict__ Wh_e, const float* __restrict__ Wi_e,
                      const float* __restrict__ emb){
    int i = blockIdx.x*blockDim.x + threadIdx.x;
    if (i < 4*Hn*Hn) g_whe_r[i] = rna_f(Wh_e[i]);
    if (i < 4*Hn*En) g_wie_r[i] = rna_f(Wi_e[i]);
    if (i < 1000*En) g_emb_r[i] = rna_f(emb[i]);
}

// post-encoder setup: round Wh_d, build wpad + decoder tables
__global__ void post_k(const float* __restrict__ Wh_d, const float* __restrict__ Wi_d,
                       const float* __restrict__ act_emb, const float* __restrict__ tgt_emb,
                       const float* __restrict__ W_a, const float* __restrict__ W_t,
                       const float* __restrict__ Wf){
    int i = blockIdx.x*blockDim.x + threadIdx.x;
    if (i < 4*Hn*Hn) g_whd_r[i] = rna_f(Wh_d[i]);
    if (i < 128*Hn){
        int r = i >> 9, k = i & 511;
        float v = 0.f;
        if (r < 8)        v = W_a[r*Hn + k];
        else if (r < 88)  v = W_t[(r-8)*Hn + k];
        else if (r == 88) v = Wf[k];
        g_wpad[i] = rna_f(v);
    }
    if (i < 88*4*Hn){
        int r = i >> 11, col = i & 2047;
        if (r < An){
            float a = 0.f; const float* w = Wi_d + col*64; const float* e = act_emb + r*EDn;
            #pragma unroll
            for (int k=0;k<EDn;k++) a += e[k]*w[k];
            g_act_z[r*4*Hn + col] = a;
        } else {
            int rr = r - An;
            float a = 0.f; const float* w = Wi_d + col*64 + EDn; const float* e = tgt_emb + rr*EDn;
            #pragma unroll
            for (int k=0;k<EDn;k++) a += e[k]*w[k];
            g_tgt_z[rr*4*Hn + col] = a;
        }
    }
}

// ---------------------------------------------------------------------------
// One-shot staged GEMMs (zx / proj). 64x128 tile, 256 thr, 8 warps.
// ---------------------------------------------------------------------------
template<int MODE>
__device__ __forceinline__ void gemm_tile(uint32_t* dsm, const float* __restrict__ Ap,
                                          int nIdx, int m0, float (&acc)[2][4][4])
{
    constexpr int NC = (MODE==0) ? 4 : 16;
    const int tid = threadIdx.x;
    const int lane = tid & 31, warp = tid >> 5;
    const int wm = warp >> 2, wn = warp & 3;
    const int c4 = lane & 3, r4 = lane >> 2;

    #pragma unroll
    for (int i=0;i<2;i++)
        #pragma unroll
        for (int j=0;j<4;j++)
            #pragma unroll
            for (int q=0;q<4;q++) acc[i][j][q]=0.f;

    auto aRow = [&](int m)->const float* {
        if (MODE==0){ int rr=m0+m; if (rr>999) rr=999; return Ap + (size_t)rr*En; }
        return Ap + (size_t)(m0+m)*Hn;
    };
    auto bRow = [&](int rn)->const float* {
        if (MODE==0) return g_wie_r + (size_t)(nIdx*128 + rn)*En;
        return g_wpad + (size_t)rn*Hn;
    };
    const uint32_t smb = smem_u32(dsm);
    auto load_chunk = [&](int c, int st){
        uint32_t base = smb + (uint32_t)st*24576u;
        int k0 = c*32;
        #pragma unroll
        for (int i=0;i<2;i++){
            int u = tid + i*256;
            int m = u>>3, g = u&7;
            CP_ASYNC16(base + (uint32_t)(m*128 + ((g^(m&7))<<4)), aRow(m) + k0 + g*4);
        }
        #pragma unroll
        for (int i=0;i<4;i++){
            int u = tid + i*256;
            int rn = u>>3, g = u&7;
            CP_ASYNC16(base + 8192u + (uint32_t)(rn*128 + ((g^(rn&7))<<4)), bRow(rn) + k0 + g*4);
        }
        CP_COMMIT();
    };

    load_chunk(0,0);
    load_chunk(1,1);

    #pragma unroll 1
    for (int c=0;c<NC;c++){
        if (c+2 < NC) load_chunk(c+2, (c+2)%3);
        if (c+2 < NC) { CP_WAIT(2); } else if (c+1 < NC) { CP_WAIT(1); } else { CP_WAIT(0); }
        __syncthreads();
        const uint32_t* S = dsm + (c%3)*6144;
        #pragma unroll
        for (int ks=0;ks<4;ks++){
            int sw0 = (((2*ks  ) ^ r4) << 2) + c4;
            int sw1 = (((2*ks+1) ^ r4) << 2) + c4;
            uint32_t a[2][4];
            #pragma unroll
            for (int i=0;i<2;i++){
                int r0 = (wm*32 + i*16 + r4)*32;
                a[i][0]=S[r0+sw0]; a[i][1]=S[r0+256+sw0];
                a[i][2]=S[r0+sw1]; a[i][3]=S[r0+256+sw1];
            }
            #pragma unroll
            for (int j=0;j<4;j++){
                int nb = wn*32 + j*8;
                int n0 = 2048 + (nb + r4)*32;
                uint32_t b0 = S[n0+sw0], b1 = S[n0+sw1];
                MMA_TF32(acc[0][j], a[0], b0, b1);
                MMA_TF32(acc[1][j], a[1], b0, b1);
            }
        }
        __syncthreads();
    }
}

__global__ __launch_bounds__(256,1) void zx_k(){
    extern __shared__ __align__(1024) uint32_t dsm[];
    const int nIdx = blockIdx.x;
    const int m0   = blockIdx.y * 64;
    const int lane = threadIdx.x & 31, warp = threadIdx.x >> 5;
    const int wm = warp >> 2, wn = warp & 3;
    const int c4 = lane & 3, r4 = lane >> 2;
    float acc[2][4][4];
    gemm_tile<0>(dsm, g_emb_r, nIdx, m0, acc);
    #pragma unroll
    for (int i=0;i<2;i++)
    #pragma unroll
    for (int rh=0;rh<2;rh++){
        int gm = m0 + wm*32 + i*16 + rh*8 + r4;
        if (gm >= 1000) continue;
        #pragma unroll
        for (int j=0;j<4;j++)
        #pragma unroll
        for (int cc=0;cc<2;cc++){
            int col = nIdx*128 + wn*32 + j*8 + c4*2 + cc;
            g_zx[(size_t)gm*2048 + col] = acc[i][j][rh*2+cc];
        }
    }
}

__global__ __launch_bounds__(256,1) void proj_k(){
    extern __shared__ __align__(1024) uint32_t dsm[];
    const int m0 = blockIdx.y * 64;
    const int lane = threadIdx.x & 31, warp = threadIdx.x >> 5;
    const int wm = warp >> 2, wn = warp & 3;
    const int c4 = lane & 3, r4 = lane >> 2;
    float acc[2][4][4];
    gemm_tile<3>(dsm, g_enc_out, 0, m0, acc);
    #pragma unroll
    for (int i=0;i<2;i++)
    #pragma unroll
    for (int rh=0;rh<2;rh++){
        int gm = m0 + wm*32 + i*16 + rh*8 + r4;
        #pragma unroll
        for (int j=0;j<4;j++)
        #pragma unroll
        for (int cc=0;cc<2;cc++){
            int col = wn*32 + j*8 + c4*2 + cc;
            if (col < 96) g_P[(size_t)gm*96 + col] = acc[i][j][rh*2+cc];
        }
    }
}

// ---------------------------------------------------------------------------
// Persistent step kernel: 128 CTAs x 256 thr.
// Split-K warp pairing: 8 warps = 4 output tiles (32x32) x 2 K-slices.
// Warp w: tile tm=(w&3)>>1, tn=w&1 ; kslice=w>>2 handles ks {2k,2k+1}/chunk.
// Per-chunk CTA LDS: 32KB (A x2, B x2) == MMA floor.
// End of step: 16KB smem partial exchange; warp owns i-half == its kslice.
// smem: A ring 4x8KB @u32[0..8192) ; B 16x8KB @u32[8192..40960)
// exchange buffer reuses dsm[0..4096).
// ---------------------------------------------------------------------------
template<int MODE>  // 1 = encoder, 2 = decoder
__global__ __launch_bounds__(256,1) void step_persist_k(
    const float* __restrict__ bias, const int* __restrict__ enc_input,
    const float* __restrict__ Wf, const float* __restrict__ bfv,
    const float* __restrict__ b_a, const float* __restrict__ b_t,
    float* __restrict__ out)
{
    extern __shared__ __align__(1024) uint32_t dsm[];
    __shared__ float shw[256], red[256], pp[256], shp[96];
    const int tid = threadIdx.x;
    const int lane = tid & 31, wid = tid >> 5;
    const int tm = (wid & 3) >> 1, tn = wid & 1, kslice = wid >> 2;
    const int c4 = lane & 3, r4 = lane >> 2;
    const int nIdx = blockIdx.x >> 2;
    const int mgrp = blockIdx.x & 3;
    const int m0   = mgrp * 64;
    const uint32_t smb = smem_u32(dsm);
    const int NSTEP = (MODE==1) ? Sn : Tn;

    // persistent weight slice: rows rn = gate*16 + unit
    {
        const float* W = (MODE==1) ? g_whe_r : g_whd_r;
        #pragma unroll 1
        for (int ch=0; ch<16; ch++){
            #pragma unroll
            for (int i=0;i<2;i++){
                int u = tid + i*256;
                int rn = u>>3, g = u&7;
                int gate = rn>>4, ul = rn&15;
                const float* src = W + (size_t)(gate*Hn + nIdx*16 + ul)*Hn + ch*32 + g*4;
                CP_ASYNC16(smb + 32768u + (uint32_t)(ch*8192 + rn*128 + ((g^(rn&7))<<4)), src);
            }
        }
        CP_COMMIT();
    }

    auto loadA = [&](const float* hin, int c, int st){
        uint32_t base = smb + (uint32_t)st*8192u;
        int k0 = c*32;
        #pragma unroll
        for (int i=0;i<2;i++){
            int u = tid + i*256;
            int m = u>>3, g = u&7;
            CP_ASYNC16(base + (uint32_t)(m*128 + ((g^(m&7))<<4)),
                       hin + (size_t)(m0+m)*Hn + k0 + g*4);
        }
        CP_COMMIT();
    };

    float acc[2][4][4];

    #pragma unroll 1
    for (int t=0; t<NSTEP; t++){
        int par = t & 1;
        const float* hin = g_h[par];

        #pragma unroll
        for (int i=0;i<2;i++)
            #pragma unroll
            for (int j=0;j<4;j++)
                #pragma unroll
                for (int q=0;q<4;q++) acc[i][j][q]=0.f;

        loadA(hin, 0, 0);
        loadA(hin, 1, 1);
        #pragma unroll 1
        for (int c=0;c<16;c++){
            if (c+2 < 16) loadA(hin, c+2, (c+2)&3);
            if (c+2 < 16) { CP_WAIT(2); } else if (c+1 < 16) { CP_WAIT(1); } else { CP_WAIT(0); }
            __syncthreads();
            const uint32_t* SA = dsm + (c&3)*2048;
            const uint32_t* SB = dsm + 8192 + c*2048;
            #pragma unroll
            for (int kk=0;kk<2;kk++){
                int ks = kslice*2 + kk;
                int sw0 = (((2*ks  ) ^ r4) << 2) + c4;
                int sw1 = (((2*ks+1) ^ r4) << 2) + c4;
                uint32_t a[2][4];
                #pragma unroll
                for (int i=0;i<2;i++){
                    int r0 = (tm*32 + i*16 + r4)*32;
                    a[i][0]=SA[r0+sw0]; a[i][1]=SA[r0+256+sw0];
                    a[i][2]=SA[r0+sw1]; a[i][3]=SA[r0+256+sw1];
                }
                #pragma unroll
                for (int j=0;j<4;j++){
                    int n0 = (j*16 + tn*8 + r4)*32;
                    uint32_t b0 = SB[n0+sw0], b1 = SB[n0+sw1];
                    MMA_TF32(acc[0][j], a[0], b0, b1);
                    MMA_TF32(acc[1][j], a[1], b0, b1);
                }
            }
            // no trailing sync: 4-stage ring makes next loadA WAR-safe
        }

        // merge K-slice partials: warp keeps i-half == kslice, ships the other
        __syncthreads();
        {
            float4* ex = (float4*)dsm;
            int io = 1 - kslice;
            #pragma unroll
            for (int j=0;j<4;j++)
                ex[(j*8 + wid)*32 + lane] =
                    make_float4(acc[io][j][0],acc[io][j][1],acc[io][j][2],acc[io][j][3]);
        }
        __syncthreads();
        {
            const float4* ex = (const float4*)dsm;
            #pragma unroll
            for (int j=0;j<4;j++){
                float4 v = ex[(j*8 + (wid^4))*32 + lane];
                acc[kslice][j][0]+=v.x; acc[kslice][j][1]+=v.y;
                acc[kslice][j][2]+=v.z; acc[kslice][j][3]+=v.w;
            }
        }

        // LSTM epilogue: warp covers rows tm*32 + kslice*16 + rh*8 + r4
        #pragma unroll
        for (int rh=0;rh<2;rh++){
            int bg = m0 + tm*32 + kslice*16 + rh*8 + r4;
            const float *x0, *x1 = nullptr;
            if (MODE==1){ x0 = g_zx + (size_t)enc_input[bg*Sn + t]*2048; }
            else { x0 = g_act_z + (size_t)g_inp[bg*2]*2048;
                   x1 = g_tgt_z + (size_t)g_inp[bg*2+1]*2048; }
            float* hout = g_h[par^1] + (size_t)bg*Hn;
            float* crow = g_c + (size_t)bg*Hn;
            float* eout = g_enc_out + ((size_t)t*Bn + bg)*Hn;
            #pragma unroll
            for (int cc=0;cc<2;cc++){
                int u = nIdx*16 + tn*8 + c4*2 + cc;
                int q = rh*2 + cc;
                float xi, xf, xg, xo;
                if (MODE==1){ xi=x0[u]; xf=x0[512+u]; xg=x0[1024+u]; xo=x0[1536+u]; }
                else { xi=x0[u]+x1[u]; xf=x0[512+u]+x1[512+u];
                       xg=x0[1024+u]+x1[1024+u]; xo=x0[1536+u]+x1[1536+u]; }
                float zi = acc[kslice][0][q] + bias[       u] + xi;
                float zf = acc[kslice][1][q] + bias[ 512 + u] + xf;
                float zg = acc[kslice][2][q] + bias[1024 + u] + xg;
                float zo = acc[kslice][3][q] + bias[1536 + u] + xo;
                float co = crow[u];
                float cn = sigmoidf_(zf)*co + sigmoidf_(zi)*tanhf(zg);
                crow[u] = cn;
                float hn = rna_f(sigmoidf_(zo)*tanhf(cn));
                hout[u] = hn;
                if (MODE==1) eout[u] = hn;
            }
        }

        if (MODE==1){
            gbar(mgrp*256 + t, 32);
        } else {
            gbar(1024 + 2*t, 128);
            #pragma unroll 1
            for (int rb=0;rb<2;rb++){
                int b = blockIdx.x*2 + rb;
                const float* h = g_h[par^1] + (size_t)b*Hn;

                float part = h[tid]*Wf[512+tid] + h[tid+256]*Wf[768+tid];
                red[tid] = part; __syncthreads();
                for (int o=128;o;o>>=1){ if (tid<o) red[tid]+=red[tid+o]; __syncthreads(); }
                float hdot = red[0] + bfv[0];
                __syncthreads();

                float sc = g_P[((size_t)tid*Bn + b)*96 + 88] + hdot;
                red[tid] = sc; __syncthreads();
                for (int o=128;o;o>>=1){ if (tid<o) red[tid]=fmaxf(red[tid],red[tid+o]); __syncthreads(); }
                float m = red[0]; __syncthreads();
                float e = expf(sc - m);
                red[tid] = e; __syncthreads();
                for (int o=128;o;o>>=1){ if (tid<o) red[tid]+=red[tid+o]; __syncthreads(); }
                float inv = 1.f/red[0];
                shw[tid] = e*inv;
                __syncthreads();

                if (tid < 176){
                    int col = tid >> 1, hf = tid & 1;
                    float a2 = 0.f;
                    const float* pb = g_P + (size_t)b*96 + col;
                    int s0 = hf*128;
                    #pragma unroll 4
                    for (int s=s0; s<s0+128; s++) a2 += shw[s]*pb[(size_t)s*((size_t)Bn*96)];
                    pp[tid] = a2;
                }
                __syncthreads();
                if (tid < 88){
                    float v = pp[2*tid] + pp[2*tid+1] + ((tid < An) ? b_a[tid] : b_t[tid-An]);
                    shp[tid] = v;
                    if (tid < An) out[(b*Tn + t)*An + tid] = v;
                    else          out[Bn*Tn*An + (b*Tn + t)*NTn + (tid-An)] = v;
                }
                __syncthreads();
                if (tid == 0){
                    int ia=0; float bv=shp[0];
                    #pragma unroll
                    for (int a=1;a<An;a++) if (shp[a]>bv){bv=shp[a]; ia=a;}
                    int it=0; float tv=shp[An];
                    for (int j=1;j<NTn;j++) if (shp[An+j]>tv){tv=shp[An+j]; it=j;}
                    g_inp[b*2] = ia; g_inp[b*2+1] = it;
                }
                __syncthreads();
            }
            gbar(1024 + 2*t + 1, 128);
        }
    }
}

extern "C" void kernel_launch(void* const* d_in, const int* in_sizes, int n_in,
                              void* d_out, int out_size)
{
    const int*   enc_input = (const int*)  d_in[0];
    const float* enc_embed = (const float*)d_in[2];
    const float* Wi_e      = (const float*)d_in[3];
    const float* Wh_e      = (const float*)d_in[4];
    const float* b_e       = (const float*)d_in[5];
    const float* act_emb   = (const float*)d_in[6];
    const float* tgt_emb   = (const float*)d_in[7];
    const float* Wi_d      = (const float*)d_in[8];
    const float* Wh_d      = (const float*)d_in[9];
    const float* b_d       = (const float*)d_in[10];
    const float* W_a       = (const float*)d_in[11];
    const float* b_a       = (const float*)d_in[12];
    const float* W_t       = (const float*)d_in[13];
    const float* b_t       = (const float*)d_in[14];
    const float* Wf        = (const float*)d_in[15];
    const float* bf        = (const float*)d_in[16];
    float* out = (float*)d_out;

    const int GEMM_SMEM = 3*24576;
    const int STEP_SMEM = 32768 + 131072;
    cudaFuncSetAttribute(zx_k,   cudaFuncAttributeMaxDynamicSharedMemorySize, GEMM_SMEM);
    cudaFuncSetAttribute(proj_k, cudaFuncAttributeMaxDynamicSharedMemorySize, GEMM_SMEM);
    cudaFuncSetAttribute(step_persist_k<1>, cudaFuncAttributeMaxDynamicSharedMemorySize, STEP_SMEM);
    cudaFuncSetAttribute(step_persist_k<2>, cudaFuncAttributeMaxDynamicSharedMemorySize, STEP_SMEM);

    // launch order chosen so the ENCODER is launch index 3 (ncu capture slot)
    init_k<<<(Bn*Hn + 255)/256, 256>>>();                                   // 0
    pre_k<<<4096, 256>>>(Wh_e, Wi_e, enc_embed);                            // 1
    zx_k<<<dim3(16,16), 256, GEMM_SMEM>>>();                                // 2
    step_persist_k<1><<<128, 256, STEP_SMEM>>>(b_e, enc_input, nullptr,     // 3
                                               nullptr, nullptr, nullptr, nullptr);
    post_k<<<4096, 256>>>(Wh_d, Wi_d, act_emb, tgt_emb, W_a, W_t, Wf);      // 4
    proj_k<<<dim3(1,1024), 256, GEMM_SMEM>>>();                             // 5
    step_persist_k<2><<<128, 256, STEP_SMEM>>>(b_d, nullptr, Wf, bf,        // 6
                                               b_a, b_t, out);
}

// round 14
// speedup vs baseline: 1.0446x; 1.0446x over previous
#include <cuda_runtime.h>
#include <math.h>
#include <stdint.h>

#define Bn 256
#define Sn 256
#define Tn 32
#define Hn 512
#define En 128
#define EDn 32
#define An 8
#define NTn 80

__device__ float g_h[2][Bn*Hn];
__device__ float g_c[Bn*Hn];
__device__ float g_enc_out[(size_t)Sn*Bn*Hn];
__device__ float g_zx[1000*4*Hn];
__device__ float g_act_z[An*4*Hn];
__device__ float g_tgt_z[NTn*4*Hn];
__device__ float g_P[(size_t)Sn*Bn*96];
__device__ float g_wpad[128*Hn];
__device__ float g_wie_r[4*Hn*En];
__device__ float g_whe_r[4*Hn*Hn];
__device__ float g_whd_r[4*Hn*Hn];
__device__ float g_emb_r[1000*En];
__device__ int   g_inp[Bn*2];
__device__ int   g_bar[1152];   // [0..1023] enc: mgrp*256+t ; [1024..1087] dec

__device__ __forceinline__ float sigmoidf_(float x){ return 1.f/(1.f+expf(-x)); }
__device__ __forceinline__ float rna_f(float x){
    uint32_t u; asm("cvt.rna.tf32.f32 %0, %1;" : "=r"(u) : "f"(x));
    return __uint_as_float(u);
}
__device__ __forceinline__ uint32_t smem_u32(const void* p){
    uint32_t a;
    asm("{ .reg .u64 t; cvta.to.shared.u64 t, %1; cvt.u32.u64 %0, t; }" : "=r"(a) : "l"(p));
    return a;
}
#define CP_ASYNC16(dst, src) \
    asm volatile("cp.async.cg.shared.global [%0], [%1], 16;" :: "r"(dst), "l"(src))
#define CP_COMMIT() asm volatile("cp.async.commit_group;" ::: "memory")
#define CP_WAIT(n)  asm volatile("cp.async.wait_group %0;" :: "n"(n) : "memory")
#define MMA_TF32(d, a, b0v, b1v) \
    asm volatile("mma.sync.aligned.m16n8k8.row.col.f32.tf32.tf32.f32 " \
        "{%0,%1,%2,%3}, {%4,%5,%6,%7}, {%8,%9}, {%0,%1,%2,%3};" \
        : "+f"((d)[0]),"+f"((d)[1]),"+f"((d)[2]),"+f"((d)[3]) \
        : "r"((a)[0]),"r"((a)[1]),"r"((a)[2]),"r"((a)[3]), "r"(b0v),"r"(b1v))

__device__ __forceinline__ void gbar(int idx, int nc){
    __syncthreads();
    if (threadIdx.x == 0){
        int* p = &g_bar[idx];
        asm volatile("red.release.gpu.global.add.u32 [%0], 1;" :: "l"(p) : "memory");
        uint32_t v;
        do {
            asm volatile("ld.acquire.gpu.global.u32 %0, [%1];" : "=r"(v) : "l"(p) : "memory");
        } while (v < (uint32_t)nc);
    }
    __syncthreads();
}

__global__ void init_k(){
    int i = blockIdx.x*blockDim.x + threadIdx.x;
    if (i < Bn*Hn){ g_h[0][i]=0.f; g_h[1][i]=0.f; g_c[i]=0.f; }
    if (i < Bn*2) g_inp[i]=0;
    if (i < 1152) g_bar[i]=0;
}

__global__ void pre_k(const float* __restrict__ Wh_e, const float* __restrict__ Wi_e,
                      const float* __restrict__ emb){
    int i = blockIdx.x*blockDim.x + threadIdx.x;
    if (i < 4*Hn*Hn) g_whe_r[i] = rna_f(Wh_e[i]);
    if (i < 4*Hn*En) g_wie_r[i] = rna_f(Wi_e[i]);
    if (i < 1000*En) g_emb_r[i] = rna_f(emb[i]);
}

__global__ void post_k(const float* __restrict__ Wh_d, const float* __restrict__ Wi_d,
                       const float* __restrict__ act_emb, const float* __restrict__ tgt_emb,
                       const float* __restrict__ W_a, const float* __restrict__ W_t,
                       const float* __restrict__ Wf){
    int i = blockIdx.x*blockDim.x + threadIdx.x;
    if (i < 4*Hn*Hn) g_whd_r[i] = rna_f(Wh_d[i]);
    if (i < 128*Hn){
        int r = i >> 9, k = i & 511;
        float v = 0.f;
        if (r < 8)        v = W_a[r*Hn + k];
        else if (r < 88)  v = W_t[(r-8)*Hn + k];
        else if (r == 88) v = Wf[k];
        g_wpad[i] = rna_f(v);
    }
    if (i < 88*4*Hn){
        int r = i >> 11, col = i & 2047;
        if (r < An){
            float a = 0.f; const float* w = Wi_d + col*64; const float* e = act_emb + r*EDn;
            #pragma unroll
            for (int k=0;k<EDn;k++) a += e[k]*w[k];
            g_act_z[r*4*Hn + col] = a;
        } else {
            int rr = r - An;
            float a = 0.f; const float* w = Wi_d + col*64 + EDn; const float* e = tgt_emb + rr*EDn;
            #pragma unroll
            for (int k=0;k<EDn;k++) a += e[k]*w[k];
            g_tgt_z[rr*4*Hn + col] = a;
        }
    }
}

// ---------------------------------------------------------------------------
// One-shot staged GEMMs (zx / proj). 64x128 tile, 256 thr, 8 warps.
// ---------------------------------------------------------------------------
template<int MODE>
__device__ __forceinline__ void gemm_tile(uint32_t* dsm, const float* __restrict__ Ap,
                                          int nIdx, int m0, float (&acc)[2][4][4])
{
    constexpr int NC = (MODE==0) ? 4 : 16;
    const int tid = threadIdx.x;
    const int lane = tid & 31, warp = tid >> 5;
    const int wm = warp >> 2, wn = warp & 3;
    const int c4 = lane & 3, r4 = lane >> 2;

    #pragma unroll
    for (int i=0;i<2;i++)
        #pragma unroll
        for (int j=0;j<4;j++)
            #pragma unroll
            for (int q=0;q<4;q++) acc[i][j][q]=0.f;

    auto aRow = [&](int m)->const float* {
        if (MODE==0){ int rr=m0+m; if (rr>999) rr=999; return Ap + (size_t)rr*En; }
        return Ap + (size_t)(m0+m)*Hn;
    };
    auto bRow = [&](int rn)->const float* {
        if (MODE==0) return g_wie_r + (size_t)(nIdx*128 + rn)*En;
        return g_wpad + (size_t)rn*Hn;
    };
    const uint32_t smb = smem_u32(dsm);
    auto load_chunk = [&](int c, int st){
        uint32_t base = smb + (uint32_t)st*24576u;
        int k0 = c*32;
        #pragma unroll
        for (int i=0;i<2;i++){
            int u = tid + i*256;
            int m = u>>3, g = u&7;
            CP_ASYNC16(base + (uint32_t)(m*128 + ((g^(m&7))<<4)), aRow(m) + k0 + g*4);
        }
        #pragma unroll
        for (int i=0;i<4;i++){
            int u = tid + i*256;
            int rn = u>>3, g = u&7;
            CP_ASYNC16(base + 8192u + (uint32_t)(rn*128 + ((g^(rn&7))<<4)), bRow(rn) + k0 + g*4);
        }
        CP_COMMIT();
    };

    load_chunk(0,0);
    load_chunk(1,1);

    #pragma unroll 1
    for (int c=0;c<NC;c++){
        if (c+2 < NC) load_chunk(c+2, (c+2)%3);
        if (c+2 < NC) { CP_WAIT(2); } else if (c+1 < NC) { CP_WAIT(1); } else { CP_WAIT(0); }
        __syncthreads();
        const uint32_t* S = dsm + (c%3)*6144;
        #pragma unroll
        for (int ks=0;ks<4;ks++){
            int sw0 = (((2*ks  ) ^ r4) << 2) + c4;
            int sw1 = (((2*ks+1) ^ r4) << 2) + c4;
            uint32_t a[2][4];
            #pragma unroll
            for (int i=0;i<2;i++){
                int r0 = (wm*32 + i*16 + r4)*32;
                a[i][0]=S[r0+sw0]; a[i][1]=S[r0+256+sw0];
                a[i][2]=S[r0+sw1]; a[i][3]=S[r0+256+sw1];
            }
            #pragma unroll
            for (int j=0;j<4;j++){
                int nb = wn*32 + j*8;
                int n0 = 2048 + (nb + r4)*32;
                uint32_t b0 = S[n0+sw0], b1 = S[n0+sw1];
                MMA_TF32(acc[0][j], a[0], b0, b1);
                MMA_TF32(acc[1][j], a[1], b0, b1);
            }
        }
        __syncthreads();
    }
}

__global__ __launch_bounds__(256,1) void zx_k(){
    extern __shared__ __align__(1024) uint32_t dsm[];
    const int nIdx = blockIdx.x;
    const int m0   = blockIdx.y * 64;
    const int lane = threadIdx.x & 31, warp = threadIdx.x >> 5;
    const int wm = warp >> 2, wn = warp & 3;
    const int c4 = lane & 3, r4 = lane >> 2;
    float acc[2][4][4];
    gemm_tile<0>(dsm, g_emb_r, nIdx, m0, acc);
    #pragma unroll
    for (int i=0;i<2;i++)
    #pragma unroll
    for (int rh=0;rh<2;rh++){
        int gm = m0 + wm*32 + i*16 + rh*8 + r4;
        if (gm >= 1000) continue;
        #pragma unroll
        for (int j=0;j<4;j++)
        #pragma unroll
        for (int cc=0;cc<2;cc++){
            int col = nIdx*128 + wn*32 + j*8 + c4*2 + cc;
            g_zx[(size_t)gm*2048 + col] = acc[i][j][rh*2+cc];
        }
    }
}

__global__ __launch_bounds__(256,1) void proj_k(){
    extern __shared__ __align__(1024) uint32_t dsm[];
    const int m0 = blockIdx.y * 64;
    const int lane = threadIdx.x & 31, warp = threadIdx.x >> 5;
    const int wm = warp >> 2, wn = warp & 3;
    const int c4 = lane & 3, r4 = lane >> 2;
    float acc[2][4][4];
    gemm_tile<3>(dsm, g_enc_out, 0, m0, acc);
    #pragma unroll
    for (int i=0;i<2;i++)
    #pragma unroll
    for (int rh=0;rh<2;rh++){
        int gm = m0 + wm*32 + i*16 + rh*8 + r4;
        #pragma unroll
        for (int j=0;j<4;j++)
        #pragma unroll
        for (int cc=0;cc<2;cc++){
            int col = wn*32 + j*8 + c4*2 + cc;
            if (col < 96) g_P[(size_t)gm*96 + col] = acc[i][j][rh*2+cc];
        }
    }
}

// ---------------------------------------------------------------------------
// Persistent step kernel: 128 CTAs x 256 thr, warp 16x32 (R11 GEMM shape).
// A ring: 8 stages x 8KB, prefetch depth 6 (empty commit groups at tail keep
// CP_WAIT(6) invariant). B persistent: 16 x 8KB.
// smem: A @u32[0..16384) ; B @u32[16384..49152)   (64KB + 128KB = 192KB)
// ---------------------------------------------------------------------------
template<int MODE>  // 1 = encoder, 2 = decoder
__global__ __launch_bounds__(256,1) void step_persist_k(
    const float* __restrict__ bias, const int* __restrict__ enc_input,
    const float* __restrict__ Wf, const float* __restrict__ bfv,
    const float* __restrict__ b_a, const float* __restrict__ b_t,
    float* __restrict__ out)
{
    extern __shared__ __align__(1024) uint32_t dsm[];
    __shared__ float shw[256], red[256], pp[256], shp[96];
    const int tid = threadIdx.x;
    const int lane = tid & 31, wid = tid >> 5;
    const int wm = wid >> 1, wn = wid & 1;
    const int c4 = lane & 3, r4 = lane >> 2;
    const int nIdx = blockIdx.x >> 2;
    const int mgrp = blockIdx.x & 3;
    const int m0   = mgrp * 64;
    const uint32_t smb = smem_u32(dsm);
    const int NSTEP = (MODE==1) ? Sn : Tn;

    // persistent weight slice: rows rn = gate*16 + unit
    {
        const float* W = (MODE==1) ? g_whe_r : g_whd_r;
        #pragma unroll 1
        for (int ch=0; ch<16; ch++){
            #pragma unroll
            for (int i=0;i<2;i++){
                int u = tid + i*256;
                int rn = u>>3, g = u&7;
                int gate = rn>>4, ul = rn&15;
                const float* src = W + (size_t)(gate*Hn + nIdx*16 + ul)*Hn + ch*32 + g*4;
                CP_ASYNC16(smb + 65536u + (uint32_t)(ch*8192 + rn*128 + ((g^(rn&7))<<4)), src);
            }
        }
        CP_COMMIT();
    }

    auto loadA = [&](const float* hin, int c, int st){
        uint32_t base = smb + (uint32_t)st*8192u;
        int k0 = c*32;
        #pragma unroll
        for (int i=0;i<2;i++){
            int u = tid + i*256;
            int m = u>>3, g = u&7;
            CP_ASYNC16(base + (uint32_t)(m*128 + ((g^(m&7))<<4)),
                       hin + (size_t)(m0+m)*Hn + k0 + g*4);
        }
        CP_COMMIT();
    };

    float acc[4][4];

    #pragma unroll 1
    for (int t=0; t<NSTEP; t++){
        int par = t & 1;
        const float* hin = g_h[par];

        #pragma unroll
        for (int j=0;j<4;j++)
            #pragma unroll
            for (int q=0;q<4;q++) acc[j][q]=0.f;

        // deep prefetch: 6 chunks in flight before first compute
        #pragma unroll
        for (int p=0;p<6;p++) loadA(hin, p, p);

        #pragma unroll 1
        for (int c=0;c<16;c++){
            if (c+6 < 16) loadA(hin, c+6, (c+6)&7);
            else          CP_COMMIT();          // empty group: keep count pattern
            CP_WAIT(6);
            __syncthreads();
            const uint32_t* SA = dsm + (c&7)*2048;
            const uint32_t* SB = dsm + 16384 + c*2048;
            #pragma unroll
            for (int ks=0;ks<4;ks++){
                int sw0 = (((2*ks  ) ^ r4) << 2) + c4;
                int sw1 = (((2*ks+1) ^ r4) << 2) + c4;
                uint32_t a[4];
                int r0 = (wm*16 + r4)*32;
                a[0]=SA[r0+sw0]; a[1]=SA[r0+256+sw0];
                a[2]=SA[r0+sw1]; a[3]=SA[r0+256+sw1];
                #pragma unroll
                for (int j=0;j<4;j++){
                    int n0 = (j*16 + wn*8 + r4)*32;
                    uint32_t b0 = SB[n0+sw0], b1 = SB[n0+sw1];
                    MMA_TF32(acc[j], a, b0, b1);
                }
            }
            // no trailing sync: 8-stage ring, writer hits stage (c-2) mod 8,
            // whose readers are fenced by iteration c-1's __syncthreads
        }

        // LSTM epilogue: all 4 gates in registers
        #pragma unroll
        for (int rh=0;rh<2;rh++){
            int bg = m0 + wm*16 + rh*8 + r4;
            const float *x0, *x1 = nullptr;
            if (MODE==1){ x0 = g_zx + (size_t)enc_input[bg*Sn + t]*2048; }
            else { x0 = g_act_z + (size_t)g_inp[bg*2]*2048;
                   x1 = g_tgt_z + (size_t)g_inp[bg*2+1]*2048; }
            float* hout = g_h[par^1] + (size_t)bg*Hn;
            float* crow = g_c + (size_t)bg*Hn;
            float* eout = g_enc_out + ((size_t)t*Bn + bg)*Hn;
            #pragma unroll
            for (int cc=0;cc<2;cc++){
                int u = nIdx*16 + wn*8 + c4*2 + cc;
                int q = rh*2 + cc;
                float xi, xf, xg, xo;
                if (MODE==1){ xi=x0[u]; xf=x0[512+u]; xg=x0[1024+u]; xo=x0[1536+u]; }
                else { xi=x0[u]+x1[u]; xf=x0[512+u]+x1[512+u];
                       xg=x0[1024+u]+x1[1024+u]; xo=x0[1536+u]+x1[1536+u]; }
                float zi = acc[0][q] + bias[       u] + xi;
                float zf = acc[1][q] + bias[ 512 + u] + xf;
                float zg = acc[2][q] + bias[1024 + u] + xg;
                float zo = acc[3][q] + bias[1536 + u] + xo;
                float co = crow[u];
                float cn = sigmoidf_(zf)*co + sigmoidf_(zi)*tanhf(zg);
                crow[u] = cn;
                float hn = rna_f(sigmoidf_(zo)*tanhf(cn));
                hout[u] = hn;
                if (MODE==1) eout[u] = hn;
            }
        }

        if (MODE==1){
            gbar(mgrp*256 + t, 32);
        } else {
            gbar(1024 + 2*t, 128);
            #pragma unroll 1
            for (int rb=0;rb<2;rb++){
                int b = blockIdx.x*2 + rb;
                const float* h = g_h[par^1] + (size_t)b*Hn;

                float part = h[tid]*Wf[512+tid] + h[tid+256]*Wf[768+tid];
                red[tid] = part; __syncthreads();
                for (int o=128;o;o>>=1){ if (tid<o) red[tid]+=red[tid+o]; __syncthreads(); }
                float hdot = red[0] + bfv[0];
                __syncthreads();

                float sc = g_P[((size_t)tid*Bn + b)*96 + 88] + hdot;
                red[tid] = sc; __syncthreads();
                for (int o=128;o;o>>=1){ if (tid<o) red[tid]=fmaxf(red[tid],red[tid+o]); __syncthreads(); }
                float m = red[0]; __syncthreads();
                float e = expf(sc - m);
                red[tid] = e; __syncthreads();
                for (int o=128;o;o>>=1){ if (tid<o) red[tid]+=red[tid+o]; __syncthreads(); }
                float inv = 1.f/red[0];
                shw[tid] = e*inv;
                __syncthreads();

                if (tid < 176){
                    int col = tid >> 1, hf = tid & 1;
                    float a2 = 0.f;
                    const float* pb = g_P + (size_t)b*96 + col;
                    int s0 = hf*128;
                    #pragma unroll 4
                    for (int s=s0; s<s0+128; s++) a2 += shw[s]*pb[(size_t)s*((size_t)Bn*96)];
                    pp[tid] = a2;
                }
                __syncthreads();
                if (tid < 88){
                    float v = pp[2*tid] + pp[2*tid+1] + ((tid < An) ? b_a[tid] : b_t[tid-An]);
                    shp[tid] = v;
                    if (tid < An) out[(b*Tn + t)*An + tid] = v;
                    else          out[Bn*Tn*An + (b*Tn + t)*NTn + (tid-An)] = v;
                }
                __syncthreads();
                if (tid == 0){
                    int ia=0; float bv=shp[0];
                    #pragma unroll
                    for (int a=1;a<An;a++) if (shp[a]>bv){bv=shp[a]; ia=a;}
                    int it=0; float tv=shp[An];
                    for (int j=1;j<NTn;j++) if (shp[An+j]>tv){tv=shp[An+j]; it=j;}
                    g_inp[b*2] = ia; g_inp[b*2+1] = it;
                }
                __syncthreads();
            }
            gbar(1024 + 2*t + 1, 128);
        }
    }
}

extern "C" void kernel_launch(void* const* d_in, const int* in_sizes, int n_in,
                              void* d_out, int out_size)
{
    const int*   enc_input = (const int*)  d_in[0];
    const float* enc_embed = (const float*)d_in[2];
    const float* Wi_e      = (const float*)d_in[3];
    const float* Wh_e      = (const float*)d_in[4];
    const float* b_e       = (const float*)d_in[5];
    const float* act_emb   = (const float*)d_in[6];
    const float* tgt_emb   = (const float*)d_in[7];
    const float* Wi_d      = (const float*)d_in[8];
    const float* Wh_d      = (const float*)d_in[9];
    const float* b_d       = (const float*)d_in[10];
    const float* W_a       = (const float*)d_in[11];
    const float* b_a       = (const float*)d_in[12];
    const float* W_t       = (const float*)d_in[13];
    const float* b_t       = (const float*)d_in[14];
    const float* Wf        = (const float*)d_in[15];
    const float* bf        = (const float*)d_in[16];
    float* out = (float*)d_out;

    const int GEMM_SMEM = 3*24576;
    const int STEP_SMEM = 65536 + 131072;   // 192KB
    cudaFuncSetAttribute(zx_k,   cudaFuncAttributeMaxDynamicSharedMemorySize, GEMM_SMEM);
    cudaFuncSetAttribute(proj_k, cudaFuncAttributeMaxDynamicSharedMemorySize, GEMM_SMEM);
    cudaFuncSetAttribute(step_persist_k<1>, cudaFuncAttributeMaxDynamicSharedMemorySize, STEP_SMEM);
    cudaFuncSetAttribute(step_persist_k<2>, cudaFuncAttributeMaxDynamicSharedMemorySize, STEP_SMEM);

    // launch order: encoder is launch index 3 (ncu capture slot)
    init_k<<<(Bn*Hn + 255)/256, 256>>>();                                   // 0
    pre_k<<<4096, 256>>>(Wh_e, Wi_e, enc_embed);                            // 1
    zx_k<<<dim3(16,16), 256, GEMM_SMEM>>>();                                // 2
    step_persist_k<1><<<128, 256, STEP_SMEM>>>(b_e, enc_input, nullptr,     // 3
                                               nullptr, nullptr, nullptr, nullptr);
    post_k<<<4096, 256>>>(Wh_d, Wi_d, act_emb, tgt_emb, W_a, W_t, Wf);      // 4
    proj_k<<<dim3(1,1024), 256, GEMM_SMEM>>>();                             // 5
    step_persist_k<2><<<128, 256, STEP_SMEM>>>(b_d, nullptr, Wf, bf,        // 6
                                               b_a, b_t, out);
}

// round 15
// speedup vs baseline: 1.3371x; 1.2800x over previous
#include <cuda_runtime.h>
#include <cuda_fp16.h>
#include <math.h>
#include <stdint.h>

#define Bn 256
#define Sn 256
#define Tn 32
#define Hn 512
#define En 128
#define EDn 32
#define An 8
#define NTn 80

__device__ float  g_h[2][Bn*Hn];          // fp32 h (decoder attention)
__device__ __half g_h16[2][Bn*Hn];        // fp16 h (GEMM operand)
__device__ float  g_c[Bn*Hn];
__device__ float  g_enc_out[(size_t)Sn*Bn*Hn];
__device__ float  g_zx[1000*4*Hn];
__device__ float  g_act_z[An*4*Hn];
__device__ float  g_tgt_z[NTn*4*Hn];
__device__ float  g_P[(size_t)Sn*Bn*96];
__device__ float  g_wpad[128*Hn];
__device__ float  g_wie_r[4*Hn*En];
__device__ __half g_whe_h[4*Hn*Hn];
__device__ __half g_whd_h[4*Hn*Hn];
__device__ float  g_emb_r[1000*En];
__device__ int    g_inp[Bn*2];
__device__ int    g_bar[1152];

__device__ __forceinline__ float sigmoidf_(float x){ return 1.f/(1.f+expf(-x)); }
__device__ __forceinline__ float rna_f(float x){
    uint32_t u; asm("cvt.rna.tf32.f32 %0, %1;" : "=r"(u) : "f"(x));
    return __uint_as_float(u);
}
__device__ __forceinline__ uint32_t smem_u32(const void* p){
    uint32_t a;
    asm("{ .reg .u64 t; cvta.to.shared.u64 t, %1; cvt.u32.u64 %0, t; }" : "=r"(a) : "l"(p));
    return a;
}
#define CP_ASYNC16(dst, src) \
    asm volatile("cp.async.cg.shared.global [%0], [%1], 16;" :: "r"(dst), "l"(src))
#define CP_COMMIT() asm volatile("cp.async.commit_group;" ::: "memory")
#define CP_WAIT(n)  asm volatile("cp.async.wait_group %0;" :: "n"(n) : "memory")
#define MMA_TF32(d, a, b0v, b1v) \
    asm volatile("mma.sync.aligned.m16n8k8.row.col.f32.tf32.tf32.f32 " \
        "{%0,%1,%2,%3}, {%4,%5,%6,%7}, {%8,%9}, {%0,%1,%2,%3};" \
        : "+f"((d)[0]),"+f"((d)[1]),"+f"((d)[2]),"+f"((d)[3]) \
        : "r"((a)[0]),"r"((a)[1]),"r"((a)[2]),"r"((a)[3]), "r"(b0v),"r"(b1v))
#define MMA_F16(d, a0,a1,a2,a3, b0v,b1v) \
    asm volatile("mma.sync.aligned.m16n8k16.row.col.f32.f16.f16.f32 " \
        "{%0,%1,%2,%3}, {%4,%5,%6,%7}, {%8,%9}, {%0,%1,%2,%3};" \
        : "+f"((d)[0]),"+f"((d)[1]),"+f"((d)[2]),"+f"((d)[3]) \
        : "r"(a0),"r"(a1),"r"(a2),"r"(a3), "r"(b0v),"r"(b1v))

// word index with granule swizzle: rows of 128B = 32 u32 words, 8 granules
__device__ __forceinline__ int sidx(int r, int w){
    return r*32 + ((((w>>2) ^ (r&7)) << 2) | (w&3));
}

__device__ __forceinline__ void gbar(int idx, int nc){
    __syncthreads();
    if (threadIdx.x == 0){
        int* p = &g_bar[idx];
        asm volatile("red.release.gpu.global.add.u32 [%0], 1;" :: "l"(p) : "memory");
        uint32_t v;
        do {
            asm volatile("ld.acquire.gpu.global.u32 %0, [%1];" : "=r"(v) : "l"(p) : "memory");
        } while (v < (uint32_t)nc);
    }
    __syncthreads();
}

__global__ void init_k(){
    int i = blockIdx.x*blockDim.x + threadIdx.x;
    if (i < Bn*Hn){
        g_h[0][i]=0.f; g_h[1][i]=0.f; g_c[i]=0.f;
        g_h16[0][i]=__float2half(0.f); g_h16[1][i]=__float2half(0.f);
    }
    if (i < Bn*2) g_inp[i]=0;
    if (i < 1152) g_bar[i]=0;
}

__global__ void pre_k(const float* __restrict__ Wh_e, const float* __restrict__ Wi_e,
                      const float* __restrict__ emb){
    int i = blockIdx.x*blockDim.x + threadIdx.x;
    if (i < 4*Hn*Hn) g_whe_h[i] = __float2half_rn(Wh_e[i]);
    if (i < 4*Hn*En) g_wie_r[i] = rna_f(Wi_e[i]);
    if (i < 1000*En) g_emb_r[i] = rna_f(emb[i]);
}

__global__ void post_k(const float* __restrict__ Wh_d, const float* __restrict__ Wi_d,
                       const float* __restrict__ act_emb, const float* __restrict__ tgt_emb,
                       const float* __restrict__ W_a, const float* __restrict__ W_t,
                       const float* __restrict__ Wf){
    int i = blockIdx.x*blockDim.x + threadIdx.x;
    if (i < 4*Hn*Hn) g_whd_h[i] = __float2half_rn(Wh_d[i]);
    if (i < 128*Hn){
        int r = i >> 9, k = i & 511;
        float v = 0.f;
        if (r < 8)        v = W_a[r*Hn + k];
        else if (r < 88)  v = W_t[(r-8)*Hn + k];
        else if (r == 88) v = Wf[k];
        g_wpad[i] = rna_f(v);
    }
    if (i < 88*4*Hn){
        int r = i >> 11, col = i & 2047;
        if (r < An){
            float a = 0.f; const float* w = Wi_d + col*64; const float* e = act_emb + r*EDn;
            #pragma unroll
            for (int k=0;k<EDn;k++) a += e[k]*w[k];
            g_act_z[r*4*Hn + col] = a;
        } else {
            int rr = r - An;
            float a = 0.f; const float* w = Wi_d + col*64 + EDn; const float* e = tgt_emb + rr*EDn;
            #pragma unroll
            for (int k=0;k<EDn;k++) a += e[k]*w[k];
            g_tgt_z[rr*4*Hn + col] = a;
        }
    }
}

// ---------------------------------------------------------------------------
// One-shot staged tf32 GEMMs (zx / proj) — unchanged proven code.
// ---------------------------------------------------------------------------
template<int MODE>
__device__ __forceinline__ void gemm_tile(uint32_t* dsm, const float* __restrict__ Ap,
                                          int nIdx, int m0, float (&acc)[2][4][4])
{
    constexpr int NC = (MODE==0) ? 4 : 16;
    const int tid = threadIdx.x;
    const int lane = tid & 31, warp = tid >> 5;
    const int wm = warp >> 2, wn = warp & 3;
    const int c4 = lane & 3, r4 = lane >> 2;

    #pragma unroll
    for (int i=0;i<2;i++)
        #pragma unroll
        for (int j=0;j<4;j++)
            #pragma unroll
            for (int q=0;q<4;q++) acc[i][j][q]=0.f;

    auto aRow = [&](int m)->const float* {
        if (MODE==0){ int rr=m0+m; if (rr>999) rr=999; return Ap + (size_t)rr*En; }
        return Ap + (size_t)(m0+m)*Hn;
    };
    auto bRow = [&](int rn)->const float* {
        if (MODE==0) return g_wie_r + (size_t)(nIdx*128 + rn)*En;
        return g_wpad + (size_t)rn*Hn;
    };
    const uint32_t smb = smem_u32(dsm);
    auto load_chunk = [&](int c, int st){
        uint32_t base = smb + (uint32_t)st*24576u;
        int k0 = c*32;
        #pragma unroll
        for (int i=0;i<2;i++){
            int u = tid + i*256;
            int m = u>>3, g = u&7;
            CP_ASYNC16(base + (uint32_t)(m*128 + ((g^(m&7))<<4)), aRow(m) + k0 + g*4);
        }
        #pragma unroll
        for (int i=0;i<4;i++){
            int u = tid + i*256;
            int rn = u>>3, g = u&7;
            CP_ASYNC16(base + 8192u + (uint32_t)(rn*128 + ((g^(rn&7))<<4)), bRow(rn) + k0 + g*4);
        }
        CP_COMMIT();
    };

    load_chunk(0,0);
    load_chunk(1,1);

    #pragma unroll 1
    for (int c=0;c<NC;c++){
        if (c+2 < NC) load_chunk(c+2, (c+2)%3);
        if (c+2 < NC) { CP_WAIT(2); } else if (c+1 < NC) { CP_WAIT(1); } else { CP_WAIT(0); }
        __syncthreads();
        const uint32_t* S = dsm + (c%3)*6144;
        #pragma unroll
        for (int ks=0;ks<4;ks++){
            int sw0 = (((2*ks  ) ^ r4) << 2) + c4;
            int sw1 = (((2*ks+1) ^ r4) << 2) + c4;
            uint32_t a[2][4];
            #pragma unroll
            for (int i=0;i<2;i++){
                int r0 = (wm*32 + i*16 + r4)*32;
                a[i][0]=S[r0+sw0]; a[i][1]=S[r0+256+sw0];
                a[i][2]=S[r0+sw1]; a[i][3]=S[r0+256+sw1];
            }
            #pragma unroll
            for (int j=0;j<4;j++){
                int nb = wn*32 + j*8;
                int n0 = 2048 + (nb + r4)*32;
                uint32_t b0 = S[n0+sw0], b1 = S[n0+sw1];
                MMA_TF32(acc[0][j], a[0], b0, b1);
                MMA_TF32(acc[1][j], a[1], b0, b1);
            }
        }
        __syncthreads();
    }
}

__global__ __launch_bounds__(256,1) void zx_k(){
    extern __shared__ __align__(1024) uint32_t dsm[];
    const int nIdx = blockIdx.x;
    const int m0   = blockIdx.y * 64;
    const int lane = threadIdx.x & 31, warp = threadIdx.x >> 5;
    const int wm = warp >> 2, wn = warp & 3;
    const int c4 = lane & 3, r4 = lane >> 2;
    float acc[2][4][4];
    gemm_tile<0>(dsm, g_emb_r, nIdx, m0, acc);
    #pragma unroll
    for (int i=0;i<2;i++)
    #pragma unroll
    for (int rh=0;rh<2;rh++){
        int gm = m0 + wm*32 + i*16 + rh*8 + r4;
        if (gm >= 1000) continue;
        #pragma unroll
        for (int j=0;j<4;j++)
        #pragma unroll
        for (int cc=0;cc<2;cc++){
            int col = nIdx*128 + wn*32 + j*8 + c4*2 + cc;
            g_zx[(size_t)gm*2048 + col] = acc[i][j][rh*2+cc];
        }
    }
}

__global__ __launch_bounds__(256,1) void proj_k(){
    extern __shared__ __align__(1024) uint32_t dsm[];
    const int m0 = blockIdx.y * 64;
    const int lane = threadIdx.x & 31, warp = threadIdx.x >> 5;
    const int wm = warp >> 2, wn = warp & 3;
    const int c4 = lane & 3, r4 = lane >> 2;
    float acc[2][4][4];
    gemm_tile<3>(dsm, g_enc_out, 0, m0, acc);
    #pragma unroll
    for (int i=0;i<2;i++)
    #pragma unroll
    for (int rh=0;rh<2;rh++){
        int gm = m0 + wm*32 + i*16 + rh*8 + r4;
        #pragma unroll
        for (int j=0;j<4;j++)
        #pragma unroll
        for (int cc=0;cc<2;cc++){
            int col = wn*32 + j*8 + c4*2 + cc;
            if (col < 96) g_P[(size_t)gm*96 + col] = acc[i][j][rh*2+cc];
        }
    }
}

// ---------------------------------------------------------------------------
// Persistent step kernel — fp16 m16n8k16 core.
// 128 CTAs x 256 thr; warp tile 16 rows x 32 cols (4 gates x 8 units).
// K=512 in 8 chunks of 64 (rows = 128B fp16, same swizzle geometry).
// A ring: 6 stages x 8KB = 48KB @[0..12288) u32; B resident: 8 x 8KB @[12288..28672).
// ---------------------------------------------------------------------------
template<int MODE>  // 1 = encoder, 2 = decoder
__global__ __launch_bounds__(256,1) void step_persist_k(
    const float* __restrict__ bias, const int* __restrict__ enc_input,
    const float* __restrict__ Wf, const float* __restrict__ bfv,
    const float* __restrict__ b_a, const float* __restrict__ b_t,
    float* __restrict__ out)
{
    extern __shared__ __align__(1024) uint32_t dsm[];
    __shared__ float shw[256], red[256], pp[256], shp[96];
    const int tid = threadIdx.x;
    const int lane = tid & 31, wid = tid >> 5;
    const int wm = wid >> 1, wn = wid & 1;
    const int c4 = lane & 3, r4 = lane >> 2;
    const int nIdx = blockIdx.x >> 2;
    const int mgrp = blockIdx.x & 3;
    const int m0   = mgrp * 64;
    const uint32_t smb = smem_u32(dsm);
    const int NSTEP = (MODE==1) ? Sn : Tn;

    // persistent fp16 weight slice: 8 chunks x (64 rows x 128B)
    {
        const __half* W16 = (MODE==1) ? g_whe_h : g_whd_h;
        #pragma unroll 1
        for (int ch=0; ch<8; ch++){
            #pragma unroll
            for (int i=0;i<2;i++){
                int u = tid + i*256;
                int rn = u>>3, g = u&7;
                int gate = rn>>4, ul = rn&15;
                const __half* src = W16 + (size_t)(gate*Hn + nIdx*16 + ul)*Hn + ch*64 + g*8;
                CP_ASYNC16(smb + 49152u + (uint32_t)(ch*8192 + rn*128 + ((g^(rn&7))<<4)), src);
            }
        }
        CP_COMMIT();
    }

    auto loadA = [&](const __half* hin, int c, int st){
        uint32_t base = smb + (uint32_t)st*8192u;
        int k0 = c*64;
        #pragma unroll
        for (int i=0;i<2;i++){
            int u = tid + i*256;
            int m = u>>3, g = u&7;
            CP_ASYNC16(base + (uint32_t)(m*128 + ((g^(m&7))<<4)),
                       hin + (size_t)(m0+m)*Hn + k0 + g*8);
        }
        CP_COMMIT();
    };

    float acc[4][4];

    #pragma unroll 1
    for (int t=0; t<NSTEP; t++){
        int par = t & 1;
        const __half* hin = g_h16[par];

        #pragma unroll
        for (int j=0;j<4;j++)
            #pragma unroll
            for (int q=0;q<4;q++) acc[j][q]=0.f;

        #pragma unroll
        for (int p=0;p<4;p++) loadA(hin, p, p);

        #pragma unroll 1
        for (int c=0;c<8;c++){
            if (c+4 < 8) loadA(hin, c+4, (c+4)%6);
            else         CP_COMMIT();
            CP_WAIT(4);
            __syncthreads();
            const uint32_t* SA = dsm + (c%6)*2048;
            const uint32_t* SB = dsm + 12288 + c*2048;
            #pragma unroll
            for (int ks=0;ks<4;ks++){
                int w0 = ks*8 + c4, w1 = w0 + 4;
                int rA0 = wm*16 + r4, rA1 = rA0 + 8;
                uint32_t a0 = SA[sidx(rA0,w0)], a1 = SA[sidx(rA1,w0)];
                uint32_t a2 = SA[sidx(rA0,w1)], a3 = SA[sidx(rA1,w1)];
                #pragma unroll
                for (int j=0;j<4;j++){
                    int cb = j*16 + wn*8 + r4;
                    uint32_t b0 = SB[sidx(cb,w0)], b1 = SB[sidx(cb,w1)];
                    MMA_F16(acc[j], a0,a1,a2,a3, b0,b1);
                }
            }
            // no trailing sync: 6-stage ring, writer stage (c+4)%6 == (c-2)%6
        }

        // LSTM epilogue: all 4 gates in registers
        #pragma unroll
        for (int rh=0;rh<2;rh++){
            int bg = m0 + wm*16 + rh*8 + r4;
            const float *x0, *x1 = nullptr;
            if (MODE==1){ x0 = g_zx + (size_t)enc_input[bg*Sn + t]*2048; }
            else { x0 = g_act_z + (size_t)g_inp[bg*2]*2048;
                   x1 = g_tgt_z + (size_t)g_inp[bg*2+1]*2048; }
            __half* hout16 = g_h16[par^1] + (size_t)bg*Hn;
            float*  crow   = g_c + (size_t)bg*Hn;
            float*  eout   = g_enc_out + ((size_t)t*Bn + bg)*Hn;
            float*  houtf  = g_h[par^1] + (size_t)bg*Hn;
            #pragma unroll
            for (int cc=0;cc<2;cc++){
                int u = nIdx*16 + wn*8 + c4*2 + cc;
                int q = rh*2 + cc;
                float xi, xf, xg, xo;
                if (MODE==1){ xi=x0[u]; xf=x0[512+u]; xg=x0[1024+u]; xo=x0[1536+u]; }
                else { xi=x0[u]+x1[u]; xf=x0[512+u]+x1[512+u];
                       xg=x0[1024+u]+x1[1024+u]; xo=x0[1536+u]+x1[1536+u]; }
                float zi = acc[0][q] + bias[       u] + xi;
                float zf = acc[1][q] + bias[ 512 + u] + xf;
                float zg = acc[2][q] + bias[1024 + u] + xg;
                float zo = acc[3][q] + bias[1536 + u] + xo;
                float co = crow[u];
                float cn = sigmoidf_(zf)*co + sigmoidf_(zi)*tanhf(zg);
                crow[u] = cn;
                __half hh = __float2half_rn(sigmoidf_(zo)*tanhf(cn));
                float  hn = __half2float(hh);
                hout16[u] = hh;
                if (MODE==1) eout[u] = hn;
                else         houtf[u] = hn;
            }
        }

        if (MODE==1){
            gbar(mgrp*256 + t, 32);
        } else {
            gbar(1024 + 2*t, 128);
            #pragma unroll 1
            for (int rb=0;rb<2;rb++){
                int b = blockIdx.x*2 + rb;
                const float* h = g_h[par^1] + (size_t)b*Hn;

                float part = h[tid]*Wf[512+tid] + h[tid+256]*Wf[768+tid];
                red[tid] = part; __syncthreads();
                for (int o=128;o;o>>=1){ if (tid<o) red[tid]+=red[tid+o]; __syncthreads(); }
                float hdot = red[0] + bfv[0];
                __syncthreads();

                float sc = g_P[((size_t)tid*Bn + b)*96 + 88] + hdot;
                red[tid] = sc; __syncthreads();
                for (int o=128;o;o>>=1){ if (tid<o) red[tid]=fmaxf(red[tid],red[tid+o]); __syncthreads(); }
                float m = red[0]; __syncthreads();
                float e = expf(sc - m);
                red[tid] = e; __syncthreads();
                for (int o=128;o;o>>=1){ if (tid<o) red[tid]+=red[tid+o]; __syncthreads(); }
                float inv = 1.f/red[0];
                shw[tid] = e*inv;
                __syncthreads();

                if (tid < 176){
                    int col = tid >> 1, hf = tid & 1;
                    const float* pb = g_P + (size_t)b*96 + col;
                    const size_t stride = (size_t)Bn*96;
                    int s0 = hf*128;
                    float a0=0.f,a1=0.f,a2=0.f,a3=0.f;
                    #pragma unroll 4
                    for (int s=s0; s<s0+128; s+=4){
                        a0 += shw[s  ]*pb[(size_t)(s  )*stride];
                        a1 += shw[s+1]*pb[(size_t)(s+1)*stride];
                        a2 += shw[s+2]*pb[(size_t)(s+2)*stride];
                        a3 += shw[s+3]*pb[(size_t)(s+3)*stride];
                    }
                    pp[tid] = (a0+a1)+(a2+a3);
                }
                __syncthreads();
                if (tid < 88){
                    float v = pp[2*tid] + pp[2*tid+1] + ((tid < An) ? b_a[tid] : b_t[tid-An]);
                    shp[tid] = v;
                    if (tid < An) out[(b*Tn + t)*An + tid] = v;
                    else          out[Bn*Tn*An + (b*Tn + t)*NTn + (tid-An)] = v;
                }
                __syncthreads();
                if (tid == 0){
                    int ia=0; float bv=shp[0];
                    #pragma unroll
                    for (int a=1;a<An;a++) if (shp[a]>bv){bv=shp[a]; ia=a;}
                    int it=0; float tv=shp[An];
                    for (int j=1;j<NTn;j++) if (shp[An+j]>tv){tv=shp[An+j]; it=j;}
                    g_inp[b*2] = ia; g_inp[b*2+1] = it;
                }
                __syncthreads();
            }
            gbar(1024 + 2*t + 1, 128);
        }
    }
}

extern "C" void kernel_launch(void* const* d_in, const int* in_sizes, int n_in,
                              void* d_out, int out_size)
{
    const int*   enc_input = (const int*)  d_in[0];
    const float* enc_embed = (const float*)d_in[2];
    const float* Wi_e      = (const float*)d_in[3];
    const float* Wh_e      = (const float*)d_in[4];
    const float* b_e       = (const float*)d_in[5];
    const float* act_emb   = (const float*)d_in[6];
    const float* tgt_emb   = (const float*)d_in[7];
    const float* Wi_d      = (const float*)d_in[8];
    const float* Wh_d      = (const float*)d_in[9];
    const float* b_d       = (const float*)d_in[10];
    const float* W_a       = (const float*)d_in[11];
    const float* b_a       = (const float*)d_in[12];
    const float* W_t       = (const float*)d_in[13];
    const float* b_t       = (const float*)d_in[14];
    const float* Wf        = (const float*)d_in[15];
    const float* bf        = (const float*)d_in[16];
    float* out = (float*)d_out;

    const int GEMM_SMEM = 3*24576;
    const int STEP_SMEM = 49152 + 65536;   // 48KB A ring + 64KB weights = 112KB
    cudaFuncSetAttribute(zx_k,   cudaFuncAttributeMaxDynamicSharedMemorySize, GEMM_SMEM);
    cudaFuncSetAttribute(proj_k, cudaFuncAttributeMaxDynamicSharedMemorySize, GEMM_SMEM);
    cudaFuncSetAttribute(step_persist_k<1>, cudaFuncAttributeMaxDynamicSharedMemorySize, STEP_SMEM);
    cudaFuncSetAttribute(step_persist_k<2>, cudaFuncAttributeMaxDynamicSharedMemorySize, STEP_SMEM);

    // launch order: encoder is launch index 3 (ncu capture slot)
    init_k<<<(Bn*Hn + 255)/256, 256>>>();                                   // 0
    pre_k<<<4096, 256>>>(Wh_e, Wi_e, enc_embed);                            // 1
    zx_k<<<dim3(16,16), 256, GEMM_SMEM>>>();                                // 2
    step_persist_k<1><<<128, 256, STEP_SMEM>>>(b_e, enc_input, nullptr,     // 3
                                               nullptr, nullptr, nullptr, nullptr);
    post_k<<<4096, 256>>>(Wh_d, Wi_d, act_emb, tgt_emb, W_a, W_t, Wf);      // 4
    proj_k<<<dim3(1,1024), 256, GEMM_SMEM>>>();                             // 5
    step_persist_k<2><<<128, 256, STEP_SMEM>>>(b_d, nullptr, Wf, bf,        // 6
                                               b_a, b_t, out);
}